// round 9
// baseline (speedup 1.0000x reference)
#include <cuda_runtime.h>
#include <cuda_bf16.h>
#include <math.h>

#define NNODE  50000
#define VOCAB  401
#define MAXH   1000
#define NPAIR  (VOCAB*MAXH)
#define NQ     512
#define NZB    1408   // zero-blocks inside kInit

// ---- device scratch ----
__device__ float d_TrelW1[VOCAB*128];      // rela@W1[0:128] + b1
__device__ float d_TtimW1[MAXH*128];
__device__ float d_Tqr[NQ*64];             // rela[q_rel]@Wqr + bqr
__device__ unsigned int d_HSWSh[NNODE*32]; // bf16x2 hidden@Ws
__device__ unsigned int d_HRh[NPAIR*64];   // bf16x2 HR
__device__ unsigned int d_GAh[NPAIR*32];   // bf16x2 GA
__device__ float d_UP[NNODE*128];
__device__ float d_BOT[NNODE];

typedef unsigned long long u64;
typedef unsigned int u32;
__device__ __forceinline__ u64 pk2(float x, float y){ u64 r; asm("mov.b64 %0,{%1,%2};":"=l"(r):"f"(x),"f"(y)); return r; }
__device__ __forceinline__ void upk2(u64 v, float&x, float&y){ asm("mov.b64 {%0,%1},%2;":"=f"(x),"=f"(y):"l"(v)); }
__device__ __forceinline__ void fma2(u64&d, u64 a, u64 b){ asm("fma.rn.f32x2 %0,%1,%2,%0;":"+l"(d):"l"(a),"l"(b)); }
__device__ __forceinline__ float lrelu(float x){ return x>0.f ? x : 0.01f*x; }
__device__ __forceinline__ u32 bf2(float a, float b){ u32 r; asm("cvt.rn.bf16x2.f32 %0,%2,%1;":"=r"(r):"f"(a),"f"(b)); return r; }
__device__ __forceinline__ float2 bf2f(u32 v){ float2 r; r.x=__uint_as_float(v<<16); r.y=__uint_as_float(v&0xffff0000u); return r; }
__device__ __forceinline__ u32 s2u(const void* p){ u32 a; asm("{ .reg .u64 t; cvta.to.shared.u64 t,%1; cvt.u32.u64 %0,t; }":"=r"(a):"l"(p)); return a; }

// ===================== fused init: zero accumulators + all small tables =====================
__global__ __launch_bounds__(128) void kInit(const float* __restrict__ rela, const float* __restrict__ W1,
                                             const float* __restrict__ b1v, const float* __restrict__ pe,
                                             const float* __restrict__ Wqr, const int* __restrict__ q_rel,
                                             const float* __restrict__ bqr){
    int b=blockIdx.x, t=threadIdx.x;
    if(b<VOCAB){
        __shared__ float s[128];
        s[t]=rela[b*128+t];
        __syncthreads();
        float acc=b1v[t];
        #pragma unroll 8
        for(int i=0;i<128;i++) acc += s[i]*W1[i*128+t];
        d_TrelW1[b*128+t]=acc;
    } else if(b<VOCAB+MAXH){
        int bb=b-VOCAB;
        __shared__ float s2[32];
        if(t<32) s2[t]=pe[bb*32+t];
        __syncthreads();
        float acc=0.f;
        #pragma unroll
        for(int i=0;i<32;i++) acc += s2[i]*W1[(128+i)*128+t];
        d_TtimW1[bb*128+t]=acc;
    } else if(b<VOCAB+MAXH+NQ){
        int bb=b-(VOCAB+MAXH);
        __shared__ float s3[128];
        int rel=q_rel[bb];
        s3[t]=rela[rel*128+t];
        __syncthreads();
        if(t<64){
            float acc=bqr[t];
            #pragma unroll 8
            for(int i=0;i<128;i++) acc += s3[i]*Wqr[i*64+t];
            d_Tqr[bb*64+t]=acc;
        }
    } else {
        int zb=b-(VOCAB+MAXH+NQ);
        int i0=zb*128+t, st=NZB*128;
        float4 z={0.f,0.f,0.f,0.f};
        for(int i=i0;i<NNODE*32;i+=st) ((float4*)d_UP)[i]=z;
        for(int i=i0;i<NNODE;i+=st) d_BOT[i]=0.f;
    }
}

// ===================== fused kB + kC (interleaved block roles) =====================
#define SAS 136
#define OFF_WR 34816
#define OFF_B2 52224
#define OFF_SA 52736
#define SMEM_C (OFF_SA+34816)
#define KCB 296   // kC blocks; same count kB blocks

__device__ __forceinline__ void ldm4(u32&r0,u32&r1,u32&r2,u32&r3,u32 addr){
    asm volatile("ldmatrix.sync.aligned.m8n8.x4.shared.b16 {%0,%1,%2,%3},[%4];"
                 :"=r"(r0),"=r"(r1),"=r"(r2),"=r"(r3):"r"(addr));
}
__device__ __forceinline__ void mma16816(float* c, u32 a0,u32 a1,u32 a2,u32 a3, u32 b0,u32 b1){
    asm volatile("mma.sync.aligned.m16n8k16.row.col.f32.bf16.bf16.f32 "
        "{%0,%1,%2,%3},{%4,%5,%6,%7},{%8,%9},{%0,%1,%2,%3};"
        :"+f"(c[0]),"+f"(c[1]),"+f"(c[2]),"+f"(c[3])
        :"r"(a0),"r"(a1),"r"(a2),"r"(a3),"r"(b0),"r"(b1));
}
__device__ __forceinline__ void sts32(u32 addr, u32 v){ asm volatile("st.shared.b32 [%0],%1;"::"r"(addr),"r"(v):"memory"); }

__global__ __launch_bounds__(256) void kBC(const float* __restrict__ hidden, const float* __restrict__ Ws,
                                           const float* __restrict__ rela, const float* __restrict__ W2,
                                           const float* __restrict__ b2v, const float* __restrict__ Wr){
    extern __shared__ char smc[];
    int tid=threadIdx.x, warp=tid>>5, lane=tid&31;

    if(blockIdx.x & 1){
        // ================= kB role: hidden@Ws -> bf16 =================
        int bidx = blockIdx.x>>1;             // 0..KCB-1
        float* sW = (float*)smc;              // 128*64 floats
        float (*sX)[128] = (float(*)[128])(smc + 128*64*4);
        for(int i=tid;i<128*64;i+=256) sW[i]=Ws[i];
        __syncthreads();
        int m0=lane*2;
        for(int n=bidx*8+warp; n<NNODE; n+=KCB*8){
            *(float4*)&sX[warp][lane*4] = *(const float4*)&hidden[n*128+lane*4];
            __syncwarp();
            u64 acc=0ULL;
            #pragma unroll 16
            for(int j=0;j<128;j++){
                float v=sX[warp][j];
                u64 hvp=pk2(v,v);
                u64 w=*(const u64*)&sW[j*64+m0];
                fma2(acc,hvp,w);
            }
            float2 r; upk2(acc,r.x,r.y);
            d_HSWSh[(size_t)n*32+lane]=bf2(r.x,r.y);
            __syncwarp();
        }
        return;
    }

    // ================= kC role: pair tables via mma.sync =================
    int cidx = blockIdx.x>>1;                 // 0..KCB-1
    __nv_bfloat16* sW2 = (__nv_bfloat16*)smc;
    __nv_bfloat16* sWr = (__nv_bfloat16*)(smc+OFF_WR);
    float* sB2 = (float*)(smc+OFF_B2);

    {
        int n = tid & 127, kh = tid >> 7;
        for(int k=kh; k<128; k+=2) sW2[n*SAS+k] = __float2bfloat16(W2[k*128+n]);
        int n2 = tid & 63, kh2 = tid >> 6;
        for(int k=kh2; k<128; k+=4) sWr[n2*SAS+k] = __float2bfloat16(Wr[k*64+n2]);
        if(tid<128) sB2[tid] = b2v[tid];
    }
    __syncthreads();

    u32 sAb  = s2u(smc+OFF_SA) + warp*16*SAS*2;
    u32 sW2b = s2u(smc);
    u32 sWrb = s2u(smc+OFF_WR);

    u32 aAddr = sAb + (u32)(((lane&15)*SAS + (lane>>4)*8)*2);
    u32 bLpart = (u32)((((lane&7) + ((lane>>4)<<3))*SAS + ((lane>>3)&1)*8)*2);

    int rquad = lane>>2, lq = lane&3, cpair = lq*2;
    const int ngroup = (NPAIR+15)/16;

    for(int g=cidx*8+warp; g<ngroup; g+=KCB*8){
        int pb = g*16;
        #pragma unroll 4
        for(int rr=0; rr<16; rr++){
            int p = pb+rr; if(p>NPAIR-1) p=NPAIR-1;
            int rel=p/MAXH, tim=p-rel*MAXH;
            float4 a=*(const float4*)&d_TrelW1[rel*128+lane*4];
            float4 b=*(const float4*)&d_TtimW1[tim*128+lane*4];
            u32 lo=bf2(lrelu(a.x+b.x),lrelu(a.y+b.y));
            u32 hi=bf2(lrelu(a.z+b.z),lrelu(a.w+b.w));
            asm volatile("st.shared.v2.b32 [%0],{%1,%2};"
                         ::"r"(sAb+(u32)((rr*SAS+lane*4)*2)),"r"(lo),"r"(hi):"memory");
        }
        __syncwarp();
        float c[16][4];
        #pragma unroll
        for(int i=0;i<16;i++){ c[i][0]=0.f;c[i][1]=0.f;c[i][2]=0.f;c[i][3]=0.f; }
        #pragma unroll
        for(int kk=0;kk<8;kk++){
            u32 a0,a1,a2,a3;
            ldm4(a0,a1,a2,a3, aAddr + kk*32);
            #pragma unroll
            for(int np=0;np<8;np++){
                u32 b0,b1,b2r,b3;
                ldm4(b0,b1,b2r,b3, sW2b + bLpart + (u32)(np*16*SAS*2) + kk*32);
                mma16816(c[np*2],   a0,a1,a2,a3, b0,b1);
                mma16816(c[np*2+1], a0,a1,a2,a3, b2r,b3);
            }
        }
        {
            int p_a = pb + rquad, p_b = p_a + 8;
            int pac = p_a>NPAIR-1?NPAIR-1:p_a, pbc = p_b>NPAIR-1?NPAIR-1:p_b;
            const float* ra = rela + (pac/MAXH)*128;
            const float* rb = rela + (pbc/MAXH)*128;
            bool wa = p_a<NPAIR, wb = p_b<NPAIR;
            #pragma unroll
            for(int nt=0;nt<16;nt++){
                int col = nt*8 + cpair;
                float h0 = lrelu(c[nt][0]+sB2[col])   + __ldg(&ra[col]);
                float h1 = lrelu(c[nt][1]+sB2[col+1]) + __ldg(&ra[col+1]);
                float h2 = lrelu(c[nt][2]+sB2[col])   + __ldg(&rb[col]);
                float h3 = lrelu(c[nt][3]+sB2[col+1]) + __ldg(&rb[col+1]);
                u32 va = bf2(h0,h1), vb = bf2(h2,h3);
                if(wa) d_HRh[(size_t)p_a*64 + nt*4 + lq] = va;
                if(wb) d_HRh[(size_t)p_b*64 + nt*4 + lq] = vb;
                sts32(sAb+(u32)((rquad*SAS+col)*2),     va);
                sts32(sAb+(u32)(((rquad+8)*SAS+col)*2), vb);
            }
        }
        __syncwarp();
        float c2[8][4];
        #pragma unroll
        for(int i=0;i<8;i++){ c2[i][0]=0.f;c2[i][1]=0.f;c2[i][2]=0.f;c2[i][3]=0.f; }
        #pragma unroll
        for(int kk=0;kk<8;kk++){
            u32 a0,a1,a2,a3;
            ldm4(a0,a1,a2,a3, aAddr + kk*32);
            #pragma unroll
            for(int np=0;np<4;np++){
                u32 b0,b1,b2r,b3;
                ldm4(b0,b1,b2r,b3, sWrb + bLpart + (u32)(np*16*SAS*2) + kk*32);
                mma16816(c2[np*2],   a0,a1,a2,a3, b0,b1);
                mma16816(c2[np*2+1], a0,a1,a2,a3, b2r,b3);
            }
        }
        {
            int p_a = pb + rquad, p_b = p_a + 8;
            bool wa = p_a<NPAIR, wb = p_b<NPAIR;
            #pragma unroll
            for(int nt=0;nt<8;nt++){
                if(wa) d_GAh[(size_t)p_a*32 + nt*4 + lq] = bf2(c2[nt][0],c2[nt][1]);
                if(wb) d_GAh[(size_t)p_b*32 + nt*4 + lq] = bf2(c2[nt][2],c2[nt][3]);
            }
        }
        __syncwarp();
    }
}

// ===================== per-edge kernel (atomic scatter) =====================
__global__ __launch_bounds__(256) void kD(const int* __restrict__ edges, const float* __restrict__ hidden,
                                          const float* __restrict__ w_alpha, int nedge){
    int e_id=(blockIdx.x*blockDim.x+threadIdx.x)>>5;
    int lane=threadIdx.x&31;
    if(e_id>=nedge) return;
    const int* e = edges + (size_t)e_id*7;
    int r_idx=__ldg(e+0), rel=__ldg(e+2), sub=__ldg(e+4), obj=__ldg(e+5), tim=__ldg(e+6);
    int p = rel*MAXH + tim;
    int m0=lane*2;
    float2 g1=bf2f(__ldg(&d_HSWSh[(size_t)sub*32+lane]));
    float2 g2=bf2f(__ldg(&d_GAh[(size_t)p*32+lane]));
    float2 g3=*(const float2*)&d_Tqr[r_idx*64+m0];
    float wa0=__ldg(&w_alpha[m0]), wa1=__ldg(&w_alpha[m0+1]);
    float s = lrelu(g1.x+g2.x+g3.x)*wa0 + lrelu(g1.y+g2.y+g3.y)*wa1;
    #pragma unroll
    for(int o=16;o;o>>=1) s += __shfl_xor_sync(0xffffffffu,s,o);
    float ea=__expf(s);
    float4 hs=*(const float4*)&hidden[(size_t)sub*128+lane*4];
    uint2 hrb= *(const uint2*)&d_HRh[(size_t)p*64+lane*2];
    float2 r01=bf2f(hrb.x), r23=bf2f(hrb.y);
    float4 m;
    m.x=ea*(hs.x+r01.x); m.y=ea*(hs.y+r01.y);
    m.z=ea*(hs.z+r23.x); m.w=ea*(hs.w+r23.y);
    float* up=&d_UP[(size_t)obj*128+lane*4];
    asm volatile("red.global.add.v4.f32 [%0], {%1,%2,%3,%4};"
                 :: "l"(up),"f"(m.x),"f"(m.y),"f"(m.z),"f"(m.w) : "memory");
    if(lane==0) atomicAdd(&d_BOT[obj], ea);
}

// ===================== final GEMM =====================
__global__ __launch_bounds__(256) void kE(const float* __restrict__ Wh, float* __restrict__ out){
    extern __shared__ float sm[];
    float* sW=sm; float* sX=sm+128*128;
    for(int i=threadIdx.x;i<128*128;i+=256) sW[i]=Wh[i];
    __syncthreads();
    int warp=threadIdx.x>>5, lane=threadIdx.x&31;
    float* x=sX+warp*128;
    int k0=lane*4;
    for(int n=blockIdx.x*8+warp; n<NNODE; n+=gridDim.x*8){
        float inv=1.f/(d_BOT[n]+1e-5f);
        float4 u=*(const float4*)&d_UP[(size_t)n*128+k0];
        float4 xx; xx.x=u.x*inv; xx.y=u.y*inv; xx.z=u.z*inv; xx.w=u.w*inv;
        *(float4*)&x[k0]=xx;
        __syncwarp();
        u64 a01=0ULL, a23=0ULL;
        #pragma unroll 16
        for(int j=0;j<128;j++){
            float v=x[j];
            u64 hv=pk2(v,v);
            ulonglong2 w=*(const ulonglong2*)&sW[j*128+k0];
            fma2(a01,hv,w.x); fma2(a23,hv,w.y);
        }
        float4 r; upk2(a01,r.x,r.y); upk2(a23,r.z,r.w);
        *(float4*)&out[(size_t)n*128+k0]=r;
        __syncwarp();
    }
}

extern "C" void kernel_launch(void* const* d_in, const int* in_sizes, int n_in,
                              void* d_out, int out_size){
    const float* hidden =(const float*)d_in[0];
    const float* rela   =(const float*)d_in[1];
    const float* pe     =(const float*)d_in[2];
    const float* W1     =(const float*)d_in[3];
    const float* b1     =(const float*)d_in[4];
    const float* W2     =(const float*)d_in[5];
    const float* b2     =(const float*)d_in[6];
    const float* Ws     =(const float*)d_in[7];
    const float* Wr     =(const float*)d_in[8];
    const float* Wqr    =(const float*)d_in[9];
    const float* bqr    =(const float*)d_in[10];
    const float* w_alpha=(const float*)d_in[11];
    const float* Wh     =(const float*)d_in[12];
    const int*   q_rel  =(const int*)d_in[13];
    const int*   edges  =(const int*)d_in[14];
    float* out=(float*)d_out;
    int nedge = in_sizes[14]/7;

    int smemE = (128*128 + 8*128)*(int)sizeof(float);
    cudaFuncSetAttribute(kBC, cudaFuncAttributeMaxDynamicSharedMemorySize, SMEM_C);
    cudaFuncSetAttribute(kE, cudaFuncAttributeMaxDynamicSharedMemorySize, smemE);

    kInit<<<VOCAB+MAXH+NQ+NZB,128>>>(rela,W1,b1,pe,Wqr,q_rel,bqr);
    kBC<<<KCB*2,256,SMEM_C>>>(hidden,Ws,rela,W2,b2,Wr);
    kD<<<(nedge*32+255)/256,256>>>(edges,hidden,w_alpha,nedge);
    kE<<<296,256,smemE>>>(Wh,out);
}

// round 10
// speedup vs baseline: 1.2676x; 1.2676x over previous
#include <cuda_runtime.h>
#include <cuda_bf16.h>
#include <math.h>

#define NNODE  50000
#define VOCAB  401
#define MAXH   1000
#define NPAIR  (VOCAB*MAXH)
#define NQ     512
#define NZB    1408   // zero-blocks inside kInit

// ---- device scratch ----
__device__ float d_TrelW1[VOCAB*128];      // rela@W1[0:128] + b1
__device__ float d_TtimW1[MAXH*128];
__device__ float d_Tqr[NQ*64];             // rela[q_rel]@Wqr + bqr
__device__ unsigned int d_HSWSh[NNODE*32]; // bf16x2 hidden@Ws
__device__ unsigned int d_HRh[NPAIR*64];   // bf16x2 HR
__device__ unsigned int d_GAh[NPAIR*32];   // bf16x2 GA
__device__ float d_UP[NNODE*128];
__device__ float d_BOT[NNODE];

typedef unsigned long long u64;
typedef unsigned int u32;
__device__ __forceinline__ u64 pk2(float x, float y){ u64 r; asm("mov.b64 %0,{%1,%2};":"=l"(r):"f"(x),"f"(y)); return r; }
__device__ __forceinline__ void upk2(u64 v, float&x, float&y){ asm("mov.b64 {%0,%1},%2;":"=f"(x),"=f"(y):"l"(v)); }
__device__ __forceinline__ void fma2(u64&d, u64 a, u64 b){ asm("fma.rn.f32x2 %0,%1,%2,%0;":"+l"(d):"l"(a),"l"(b)); }
__device__ __forceinline__ float lrelu(float x){ return x>0.f ? x : 0.01f*x; }
__device__ __forceinline__ u32 bf2(float a, float b){ u32 r; asm("cvt.rn.bf16x2.f32 %0,%2,%1;":"=r"(r):"f"(a),"f"(b)); return r; }
__device__ __forceinline__ float2 bf2f(u32 v){ float2 r; r.x=__uint_as_float(v<<16); r.y=__uint_as_float(v&0xffff0000u); return r; }
__device__ __forceinline__ u32 s2u(const void* p){ u32 a; asm("{ .reg .u64 t; cvta.to.shared.u64 t,%1; cvt.u32.u64 %0,t; }":"=r"(a):"l"(p)); return a; }

// ===================== fused init: zero accumulators + all small tables =====================
__global__ __launch_bounds__(128) void kInit(const float* __restrict__ rela, const float* __restrict__ W1,
                                             const float* __restrict__ b1v, const float* __restrict__ pe,
                                             const float* __restrict__ Wqr, const int* __restrict__ q_rel,
                                             const float* __restrict__ bqr){
    int b=blockIdx.x, t=threadIdx.x;
    if(b<VOCAB){
        __shared__ float s[128];
        s[t]=rela[b*128+t];
        __syncthreads();
        float acc=b1v[t];
        #pragma unroll 8
        for(int i=0;i<128;i++) acc += s[i]*W1[i*128+t];
        d_TrelW1[b*128+t]=acc;
    } else if(b<VOCAB+MAXH){
        int bb=b-VOCAB;
        __shared__ float s2[32];
        if(t<32) s2[t]=pe[bb*32+t];
        __syncthreads();
        float acc=0.f;
        #pragma unroll
        for(int i=0;i<32;i++) acc += s2[i]*W1[(128+i)*128+t];
        d_TtimW1[bb*128+t]=acc;
    } else if(b<VOCAB+MAXH+NQ){
        int bb=b-(VOCAB+MAXH);
        __shared__ float s3[128];
        int rel=q_rel[bb];
        s3[t]=rela[rel*128+t];
        __syncthreads();
        if(t<64){
            float acc=bqr[t];
            #pragma unroll 8
            for(int i=0;i<128;i++) acc += s3[i]*Wqr[i*64+t];
            d_Tqr[bb*64+t]=acc;
        }
    } else {
        int zb=b-(VOCAB+MAXH+NQ);
        int i0=zb*128+t, st=NZB*128;
        float4 z={0.f,0.f,0.f,0.f};
        for(int i=i0;i<NNODE*32;i+=st) ((float4*)d_UP)[i]=z;
        for(int i=i0;i<NNODE;i+=st) d_BOT[i]=0.f;
    }
}

// ===================== hidden@Ws -> bf16 =====================
__global__ __launch_bounds__(256) void kB(const float* __restrict__ hidden, const float* __restrict__ Ws){
    __shared__ float sW[128*64];
    __shared__ float sX[8][128];
    for(int i=threadIdx.x;i<128*64;i+=256) sW[i]=Ws[i];
    __syncthreads();
    int warp=threadIdx.x>>5, lane=threadIdx.x&31;
    int m0=lane*2;
    for(int n=blockIdx.x*8+warp; n<NNODE; n+=gridDim.x*8){
        *(float4*)&sX[warp][lane*4] = *(const float4*)&hidden[n*128+lane*4];
        __syncwarp();
        u64 acc=0ULL;
        #pragma unroll 16
        for(int j=0;j<128;j++){
            float v=sX[warp][j];
            u64 hvp=pk2(v,v);
            u64 w=*(const u64*)&sW[j*64+m0];
            fma2(acc,hvp,w);
        }
        float2 r; upk2(acc,r.x,r.y);
        d_HSWSh[(size_t)n*32+lane]=bf2(r.x,r.y);
        __syncwarp();
    }
}

// ===================== mma.sync pair kernel =====================
#define SAS 136
#define OFF_WR 34816
#define OFF_B2 52224
#define OFF_SA 52736
#define SMEM_C (OFF_SA+34816)

__device__ __forceinline__ void ldm4(u32&r0,u32&r1,u32&r2,u32&r3,u32 addr){
    asm volatile("ldmatrix.sync.aligned.m8n8.x4.shared.b16 {%0,%1,%2,%3},[%4];"
                 :"=r"(r0),"=r"(r1),"=r"(r2),"=r"(r3):"r"(addr));
}
__device__ __forceinline__ void mma16816(float* c, u32 a0,u32 a1,u32 a2,u32 a3, u32 b0,u32 b1){
    asm volatile("mma.sync.aligned.m16n8k16.row.col.f32.bf16.bf16.f32 "
        "{%0,%1,%2,%3},{%4,%5,%6,%7},{%8,%9},{%0,%1,%2,%3};"
        :"+f"(c[0]),"+f"(c[1]),"+f"(c[2]),"+f"(c[3])
        :"r"(a0),"r"(a1),"r"(a2),"r"(a3),"r"(b0),"r"(b1));
}
__device__ __forceinline__ void sts32(u32 addr, u32 v){ asm volatile("st.shared.b32 [%0],%1;"::"r"(addr),"r"(v):"memory"); }

__global__ __launch_bounds__(256) void kC_mma(const float* __restrict__ rela, const float* __restrict__ W2,
                                              const float* __restrict__ b2v, const float* __restrict__ Wr){
    extern __shared__ char smc[];
    __nv_bfloat16* sW2 = (__nv_bfloat16*)smc;
    __nv_bfloat16* sWr = (__nv_bfloat16*)(smc+OFF_WR);
    float* sB2 = (float*)(smc+OFF_B2);
    int tid=threadIdx.x, warp=tid>>5, lane=tid&31;

    {
        int n = tid & 127, kh = tid >> 7;
        for(int k=kh; k<128; k+=2) sW2[n*SAS+k] = __float2bfloat16(W2[k*128+n]);
        int n2 = tid & 63, kh2 = tid >> 6;
        for(int k=kh2; k<128; k+=4) sWr[n2*SAS+k] = __float2bfloat16(Wr[k*64+n2]);
        if(tid<128) sB2[tid] = b2v[tid];
    }
    __syncthreads();

    u32 sAb  = s2u(smc+OFF_SA) + warp*16*SAS*2;
    u32 sW2b = s2u(smc);
    u32 sWrb = s2u(smc+OFF_WR);

    u32 aAddr = sAb + (u32)(((lane&15)*SAS + (lane>>4)*8)*2);
    u32 bLpart = (u32)((((lane&7) + ((lane>>4)<<3))*SAS + ((lane>>3)&1)*8)*2);

    int rquad = lane>>2, lq = lane&3, cpair = lq*2;
    const int ngroup = (NPAIR+15)/16;

    for(int g=blockIdx.x*8+warp; g<ngroup; g+=gridDim.x*8){
        int pb = g*16;
        #pragma unroll 4
        for(int rr=0; rr<16; rr++){
            int p = pb+rr; if(p>NPAIR-1) p=NPAIR-1;
            int rel=p/MAXH, tim=p-rel*MAXH;
            float4 a=*(const float4*)&d_TrelW1[rel*128+lane*4];
            float4 b=*(const float4*)&d_TtimW1[tim*128+lane*4];
            u32 lo=bf2(lrelu(a.x+b.x),lrelu(a.y+b.y));
            u32 hi=bf2(lrelu(a.z+b.z),lrelu(a.w+b.w));
            asm volatile("st.shared.v2.b32 [%0],{%1,%2};"
                         ::"r"(sAb+(u32)((rr*SAS+lane*4)*2)),"r"(lo),"r"(hi):"memory");
        }
        __syncwarp();
        float c[16][4];
        #pragma unroll
        for(int i=0;i<16;i++){ c[i][0]=0.f;c[i][1]=0.f;c[i][2]=0.f;c[i][3]=0.f; }
        #pragma unroll
        for(int kk=0;kk<8;kk++){
            u32 a0,a1,a2,a3;
            ldm4(a0,a1,a2,a3, aAddr + kk*32);
            #pragma unroll
            for(int np=0;np<8;np++){
                u32 b0,b1,b2r,b3;
                ldm4(b0,b1,b2r,b3, sW2b + bLpart + (u32)(np*16*SAS*2) + kk*32);
                mma16816(c[np*2],   a0,a1,a2,a3, b0,b1);
                mma16816(c[np*2+1], a0,a1,a2,a3, b2r,b3);
            }
        }
        {
            int p_a = pb + rquad, p_b = p_a + 8;
            int pac = p_a>NPAIR-1?NPAIR-1:p_a, pbc = p_b>NPAIR-1?NPAIR-1:p_b;
            const float* ra = rela + (pac/MAXH)*128;
            const float* rb = rela + (pbc/MAXH)*128;
            bool wa = p_a<NPAIR, wb = p_b<NPAIR;
            #pragma unroll
            for(int nt=0;nt<16;nt++){
                int col = nt*8 + cpair;
                float h0 = lrelu(c[nt][0]+sB2[col])   + __ldg(&ra[col]);
                float h1 = lrelu(c[nt][1]+sB2[col+1]) + __ldg(&ra[col+1]);
                float h2 = lrelu(c[nt][2]+sB2[col])   + __ldg(&rb[col]);
                float h3 = lrelu(c[nt][3]+sB2[col+1]) + __ldg(&rb[col+1]);
                u32 va = bf2(h0,h1), vb = bf2(h2,h3);
                if(wa) d_HRh[(size_t)p_a*64 + nt*4 + lq] = va;
                if(wb) d_HRh[(size_t)p_b*64 + nt*4 + lq] = vb;
                sts32(sAb+(u32)((rquad*SAS+col)*2),     va);
                sts32(sAb+(u32)(((rquad+8)*SAS+col)*2), vb);
            }
        }
        __syncwarp();
        float c2[8][4];
        #pragma unroll
        for(int i=0;i<8;i++){ c2[i][0]=0.f;c2[i][1]=0.f;c2[i][2]=0.f;c2[i][3]=0.f; }
        #pragma unroll
        for(int kk=0;kk<8;kk++){
            u32 a0,a1,a2,a3;
            ldm4(a0,a1,a2,a3, aAddr + kk*32);
            #pragma unroll
            for(int np=0;np<4;np++){
                u32 b0,b1,b2r,b3;
                ldm4(b0,b1,b2r,b3, sWrb + bLpart + (u32)(np*16*SAS*2) + kk*32);
                mma16816(c2[np*2],   a0,a1,a2,a3, b0,b1);
                mma16816(c2[np*2+1], a0,a1,a2,a3, b2r,b3);
            }
        }
        {
            int p_a = pb + rquad, p_b = p_a + 8;
            bool wa = p_a<NPAIR, wb = p_b<NPAIR;
            #pragma unroll
            for(int nt=0;nt<8;nt++){
                if(wa) d_GAh[(size_t)p_a*32 + nt*4 + lq] = bf2(c2[nt][0],c2[nt][1]);
                if(wb) d_GAh[(size_t)p_b*32 + nt*4 + lq] = bf2(c2[nt][2],c2[nt][3]);
            }
        }
        __syncwarp();
    }
}

// ===================== per-edge kernel (atomic scatter) =====================
__global__ __launch_bounds__(256) void kD(const int* __restrict__ edges, const float* __restrict__ hidden,
                                          const float* __restrict__ w_alpha, int nedge){
    int e_id=(blockIdx.x*blockDim.x+threadIdx.x)>>5;
    int lane=threadIdx.x&31;
    if(e_id>=nedge) return;
    const int* e = edges + (size_t)e_id*7;
    int r_idx=__ldg(e+0), rel=__ldg(e+2), sub=__ldg(e+4), obj=__ldg(e+5), tim=__ldg(e+6);
    int p = rel*MAXH + tim;
    int m0=lane*2;
    float2 g1=bf2f(__ldg(&d_HSWSh[(size_t)sub*32+lane]));
    float2 g2=bf2f(__ldg(&d_GAh[(size_t)p*32+lane]));
    float2 g3=*(const float2*)&d_Tqr[r_idx*64+m0];
    float wa0=__ldg(&w_alpha[m0]), wa1=__ldg(&w_alpha[m0+1]);
    float s = lrelu(g1.x+g2.x+g3.x)*wa0 + lrelu(g1.y+g2.y+g3.y)*wa1;
    #pragma unroll
    for(int o=16;o;o>>=1) s += __shfl_xor_sync(0xffffffffu,s,o);
    float ea=__expf(s);
    float4 hs=*(const float4*)&hidden[(size_t)sub*128+lane*4];
    uint2 hrb= *(const uint2*)&d_HRh[(size_t)p*64+lane*2];
    float2 r01=bf2f(hrb.x), r23=bf2f(hrb.y);
    float4 m;
    m.x=ea*(hs.x+r01.x); m.y=ea*(hs.y+r01.y);
    m.z=ea*(hs.z+r23.x); m.w=ea*(hs.w+r23.y);
    float* up=&d_UP[(size_t)obj*128+lane*4];
    asm volatile("red.global.add.v4.f32 [%0], {%1,%2,%3,%4};"
                 :: "l"(up),"f"(m.x),"f"(m.y),"f"(m.z),"f"(m.w) : "memory");
    if(lane==0) atomicAdd(&d_BOT[obj], ea);
}

// ===================== final GEMM: 8 nodes per warp (weight LDS reuse) =====================
#define KE_NW 8
#define SMEM_E ((128*128 + 8*KE_NW*128)*4)

__global__ __launch_bounds__(256) void kE(const float* __restrict__ Wh, float* __restrict__ out){
    extern __shared__ float sm[];
    float* sW=sm;                                   // 128*128
    int warp=threadIdx.x>>5, lane=threadIdx.x&31;
    float* sX=sm + 128*128 + warp*KE_NW*128;
    for(int i=threadIdx.x;i<128*128;i+=256) sW[i]=Wh[i];
    __syncthreads();
    int k0=lane*4;
    for(int base=blockIdx.x*(8*KE_NW)+warp*KE_NW; base<NNODE; base+=gridDim.x*8*KE_NW){
        #pragma unroll
        for(int nn=0;nn<KE_NW;nn++){
            int n=base+nn; int nc=(n<NNODE)?n:(NNODE-1);
            float inv=1.f/(d_BOT[nc]+1e-5f);
            float4 u=*(const float4*)&d_UP[(size_t)nc*128+k0];
            float4 xx; xx.x=u.x*inv; xx.y=u.y*inv; xx.z=u.z*inv; xx.w=u.w*inv;
            *(float4*)&sX[nn*128+k0]=xx;
        }
        __syncwarp();
        u64 a01[KE_NW], a23[KE_NW];
        #pragma unroll
        for(int nn=0;nn<KE_NW;nn++){ a01[nn]=0ULL; a23[nn]=0ULL; }
        for(int j=0;j<128;j+=4){
            float4 xv[KE_NW];
            #pragma unroll
            for(int nn=0;nn<KE_NW;nn++) xv[nn]=*(const float4*)&sX[nn*128+j];
            #pragma unroll
            for(int jj=0;jj<4;jj++){
                ulonglong2 w=*(const ulonglong2*)&sW[(j+jj)*128+k0];
                #pragma unroll
                for(int nn=0;nn<KE_NW;nn++){
                    float v = (jj==0)?xv[nn].x:(jj==1)?xv[nn].y:(jj==2)?xv[nn].z:xv[nn].w;
                    u64 hb=pk2(v,v);
                    fma2(a01[nn],hb,w.x); fma2(a23[nn],hb,w.y);
                }
            }
        }
        #pragma unroll
        for(int nn=0;nn<KE_NW;nn++){
            int n=base+nn;
            if(n<NNODE){
                float4 r; upk2(a01[nn],r.x,r.y); upk2(a23[nn],r.z,r.w);
                *(float4*)&out[(size_t)n*128+k0]=r;
            }
        }
        __syncwarp();
    }
}

extern "C" void kernel_launch(void* const* d_in, const int* in_sizes, int n_in,
                              void* d_out, int out_size){
    const float* hidden =(const float*)d_in[0];
    const float* rela   =(const float*)d_in[1];
    const float* pe     =(const float*)d_in[2];
    const float* W1     =(const float*)d_in[3];
    const float* b1     =(const float*)d_in[4];
    const float* W2     =(const float*)d_in[5];
    const float* b2     =(const float*)d_in[6];
    const float* Ws     =(const float*)d_in[7];
    const float* Wr     =(const float*)d_in[8];
    const float* Wqr    =(const float*)d_in[9];
    const float* bqr    =(const float*)d_in[10];
    const float* w_alpha=(const float*)d_in[11];
    const float* Wh     =(const float*)d_in[12];
    const int*   q_rel  =(const int*)d_in[13];
    const int*   edges  =(const int*)d_in[14];
    float* out=(float*)d_out;
    int nedge = in_sizes[14]/7;

    cudaFuncSetAttribute(kC_mma, cudaFuncAttributeMaxDynamicSharedMemorySize, SMEM_C);
    cudaFuncSetAttribute(kE, cudaFuncAttributeMaxDynamicSharedMemorySize, SMEM_E);

    kInit<<<VOCAB+MAXH+NQ+NZB,128>>>(rela,W1,b1,pe,Wqr,q_rel,bqr);
    kB<<<296,256>>>(hidden,Ws);
    kC_mma<<<296,256,SMEM_C>>>(rela,W2,b2,Wr);
    kD<<<(nedge*32+255)/256,256>>>(edges,hidden,w_alpha,nedge);
    kE<<<296,256,SMEM_E>>>(Wh,out);
}

// round 11
// speedup vs baseline: 1.3454x; 1.0614x over previous
#include <cuda_runtime.h>
#include <cuda_bf16.h>
#include <math.h>

#define NNODE  50000
#define VOCAB  401
#define MAXH   1000
#define NPAIR  (VOCAB*MAXH)
#define NQ     512
#define NZB    1408   // zero-blocks inside kInit

// ---- device scratch ----
__device__ float d_TrelW1[VOCAB*128];      // rela@W1[0:128] + b1
__device__ float d_TtimW1[MAXH*128];
__device__ unsigned int d_Tqrh[NQ*32];     // bf16x2: rela[q_rel]@Wqr + bqr
__device__ unsigned int d_HSWSh[NNODE*32]; // bf16x2 hidden@Ws
__device__ unsigned int d_HRh[NPAIR*64];   // bf16x2 HR
__device__ unsigned int d_GAh[NPAIR*32];   // bf16x2 GA
__device__ float d_UP[NNODE*128];
__device__ float d_BOT[NNODE];

typedef unsigned long long u64;
typedef unsigned int u32;
__device__ __forceinline__ u64 pk2(float x, float y){ u64 r; asm("mov.b64 %0,{%1,%2};":"=l"(r):"f"(x),"f"(y)); return r; }
__device__ __forceinline__ void upk2(u64 v, float&x, float&y){ asm("mov.b64 {%0,%1},%2;":"=f"(x),"=f"(y):"l"(v)); }
__device__ __forceinline__ void fma2(u64&d, u64 a, u64 b){ asm("fma.rn.f32x2 %0,%1,%2,%0;":"+l"(d):"l"(a),"l"(b)); }
__device__ __forceinline__ float lrelu(float x){ return x>0.f ? x : 0.01f*x; }
__device__ __forceinline__ u32 bf2(float a, float b){ u32 r; asm("cvt.rn.bf16x2.f32 %0,%2,%1;":"=r"(r):"f"(a),"f"(b)); return r; }
__device__ __forceinline__ float2 bf2f(u32 v){ float2 r; r.x=__uint_as_float(v<<16); r.y=__uint_as_float(v&0xffff0000u); return r; }
__device__ __forceinline__ u32 s2u(const void* p){ u32 a; asm("{ .reg .u64 t; cvta.to.shared.u64 t,%1; cvt.u32.u64 %0,t; }":"=r"(a):"l"(p)); return a; }

// ===================== fused init: zero accumulators + all small tables =====================
__global__ __launch_bounds__(128) void kInit(const float* __restrict__ rela, const float* __restrict__ W1,
                                             const float* __restrict__ b1v, const float* __restrict__ pe,
                                             const float* __restrict__ Wqr, const int* __restrict__ q_rel,
                                             const float* __restrict__ bqr){
    int b=blockIdx.x, t=threadIdx.x;
    if(b<VOCAB){
        __shared__ float s[128];
        s[t]=rela[b*128+t];
        __syncthreads();
        float acc=b1v[t];
        #pragma unroll 8
        for(int i=0;i<128;i++) acc += s[i]*W1[i*128+t];
        d_TrelW1[b*128+t]=acc;
    } else if(b<VOCAB+MAXH){
        int bb=b-VOCAB;
        __shared__ float s2[32];
        if(t<32) s2[t]=pe[bb*32+t];
        __syncthreads();
        float acc=0.f;
        #pragma unroll
        for(int i=0;i<32;i++) acc += s2[i]*W1[(128+i)*128+t];
        d_TtimW1[bb*128+t]=acc;
    } else if(b<VOCAB+MAXH+NQ){
        int bb=b-(VOCAB+MAXH);
        __shared__ float s3[128];
        int rel=q_rel[bb];
        s3[t]=rela[rel*128+t];
        __syncthreads();
        if(t<64){
            float acc=bqr[t];
            #pragma unroll 8
            for(int i=0;i<128;i++) acc += s3[i]*Wqr[i*64+t];
            float accn=__shfl_down_sync(0xffffffffu,acc,1);
            if((t&1)==0) d_Tqrh[bb*32+(t>>1)]=bf2(acc,accn);
        }
    } else {
        int zb=b-(VOCAB+MAXH+NQ);
        int i0=zb*128+t, st=NZB*128;
        float4 z={0.f,0.f,0.f,0.f};
        for(int i=i0;i<NNODE*32;i+=st) ((float4*)d_UP)[i]=z;
        for(int i=i0;i<NNODE;i+=st) d_BOT[i]=0.f;
    }
}

// ===================== hidden@Ws -> bf16 =====================
__global__ __launch_bounds__(256) void kB(const float* __restrict__ hidden, const float* __restrict__ Ws){
    __shared__ float sW[128*64];
    __shared__ float sX[8][128];
    for(int i=threadIdx.x;i<128*64;i+=256) sW[i]=Ws[i];
    __syncthreads();
    int warp=threadIdx.x>>5, lane=threadIdx.x&31;
    int m0=lane*2;
    for(int n=blockIdx.x*8+warp; n<NNODE; n+=gridDim.x*8){
        *(float4*)&sX[warp][lane*4] = *(const float4*)&hidden[n*128+lane*4];
        __syncwarp();
        u64 acc=0ULL;
        #pragma unroll 16
        for(int j=0;j<128;j++){
            float v=sX[warp][j];
            u64 hvp=pk2(v,v);
            u64 w=*(const u64*)&sW[j*64+m0];
            fma2(acc,hvp,w);
        }
        float2 r; upk2(acc,r.x,r.y);
        d_HSWSh[(size_t)n*32+lane]=bf2(r.x,r.y);
        __syncwarp();
    }
}

// ===================== mma.sync pair kernel =====================
#define SAS 136
#define OFF_WR 34816
#define OFF_B2 52224
#define OFF_SA 52736
#define SMEM_C (OFF_SA+34816)

__device__ __forceinline__ void ldm4(u32&r0,u32&r1,u32&r2,u32&r3,u32 addr){
    asm volatile("ldmatrix.sync.aligned.m8n8.x4.shared.b16 {%0,%1,%2,%3},[%4];"
                 :"=r"(r0),"=r"(r1),"=r"(r2),"=r"(r3):"r"(addr));
}
__device__ __forceinline__ void mma16816(float* c, u32 a0,u32 a1,u32 a2,u32 a3, u32 b0,u32 b1){
    asm volatile("mma.sync.aligned.m16n8k16.row.col.f32.bf16.bf16.f32 "
        "{%0,%1,%2,%3},{%4,%5,%6,%7},{%8,%9},{%0,%1,%2,%3};"
        :"+f"(c[0]),"+f"(c[1]),"+f"(c[2]),"+f"(c[3])
        :"r"(a0),"r"(a1),"r"(a2),"r"(a3),"r"(b0),"r"(b1));
}
__device__ __forceinline__ void sts32(u32 addr, u32 v){ asm volatile("st.shared.b32 [%0],%1;"::"r"(addr),"r"(v):"memory"); }
__device__ __forceinline__ void lds128(u32&a0,u32&a1,u32&a2,u32&a3,u32 addr){
    asm volatile("ld.shared.v4.b32 {%0,%1,%2,%3},[%4];"
                 :"=r"(a0),"=r"(a1),"=r"(a2),"=r"(a3):"r"(addr));
}

__global__ __launch_bounds__(256) void kC_mma(const float* __restrict__ rela, const float* __restrict__ W2,
                                              const float* __restrict__ b2v, const float* __restrict__ Wr){
    extern __shared__ char smc[];
    __nv_bfloat16* sW2 = (__nv_bfloat16*)smc;
    __nv_bfloat16* sWr = (__nv_bfloat16*)(smc+OFF_WR);
    float* sB2 = (float*)(smc+OFF_B2);
    int tid=threadIdx.x, warp=tid>>5, lane=tid&31;

    {
        int n = tid & 127, kh = tid >> 7;
        for(int k=kh; k<128; k+=2) sW2[n*SAS+k] = __float2bfloat16(W2[k*128+n]);
        int n2 = tid & 63, kh2 = tid >> 6;
        for(int k=kh2; k<128; k+=4) sWr[n2*SAS+k] = __float2bfloat16(Wr[k*64+n2]);
        if(tid<128) sB2[tid] = b2v[tid];
    }
    __syncthreads();

    u32 sAb  = s2u(smc+OFF_SA) + warp*16*SAS*2;
    u32 sW2b = s2u(smc);
    u32 sWrb = s2u(smc+OFF_WR);

    u32 aAddr = sAb + (u32)(((lane&15)*SAS + (lane>>4)*8)*2);
    u32 bLpart = (u32)((((lane&7) + ((lane>>4)<<3))*SAS + ((lane>>3)&1)*8)*2);

    int rquad = lane>>2, cpair = (lane&3)*2;
    const int ngroup = (NPAIR+15)/16;

    for(int g=blockIdx.x*8+warp; g<ngroup; g+=gridDim.x*8){
        int pb = g*16;
        // ---- build A: h1 = lrelu(TrelW1+TtimW1+b1) bf16 ----
        #pragma unroll 4
        for(int rr=0; rr<16; rr++){
            int p = pb+rr; if(p>NPAIR-1) p=NPAIR-1;
            int rel=p/MAXH, tim=p-rel*MAXH;
            float4 a=*(const float4*)&d_TrelW1[rel*128+lane*4];
            float4 b=*(const float4*)&d_TtimW1[tim*128+lane*4];
            u32 lo=bf2(lrelu(a.x+b.x),lrelu(a.y+b.y));
            u32 hi=bf2(lrelu(a.z+b.z),lrelu(a.w+b.w));
            asm volatile("st.shared.v2.b32 [%0],{%1,%2};"
                         ::"r"(sAb+(u32)((rr*SAS+lane*4)*2)),"r"(lo),"r"(hi):"memory");
        }
        __syncwarp();
        // ---- GEMM1 ----
        float c[16][4];
        #pragma unroll
        for(int i=0;i<16;i++){ c[i][0]=0.f;c[i][1]=0.f;c[i][2]=0.f;c[i][3]=0.f; }
        #pragma unroll
        for(int kk=0;kk<8;kk++){
            u32 a0,a1,a2,a3;
            ldm4(a0,a1,a2,a3, aAddr + kk*32);
            #pragma unroll
            for(int np=0;np<8;np++){
                u32 b0,b1,b2r,b3;
                ldm4(b0,b1,b2r,b3, sW2b + bLpart + (u32)(np*16*SAS*2) + kk*32);
                mma16816(c[np*2],   a0,a1,a2,a3, b0,b1);
                mma16816(c[np*2+1], a0,a1,a2,a3, b2r,b3);
            }
        }
        // ---- epilogue1: hr -> sA (bf16) only ----
        {
            int p_a = pb + rquad, p_b = p_a + 8;
            int pac = p_a>NPAIR-1?NPAIR-1:p_a, pbc = p_b>NPAIR-1?NPAIR-1:p_b;
            const float* ra = rela + (pac/MAXH)*128;
            const float* rb = rela + (pbc/MAXH)*128;
            #pragma unroll
            for(int nt=0;nt<16;nt++){
                int col = nt*8 + cpair;
                float h0 = lrelu(c[nt][0]+sB2[col])   + __ldg(&ra[col]);
                float h1 = lrelu(c[nt][1]+sB2[col+1]) + __ldg(&ra[col+1]);
                float h2 = lrelu(c[nt][2]+sB2[col])   + __ldg(&rb[col]);
                float h3 = lrelu(c[nt][3]+sB2[col+1]) + __ldg(&rb[col+1]);
                sts32(sAb+(u32)((rquad*SAS+col)*2),     bf2(h0,h1));
                sts32(sAb+(u32)(((rquad+8)*SAS+col)*2), bf2(h2,h3));
            }
        }
        __syncwarp();
        // ---- coalesced HR copy: 2 rows (512B) per iteration ----
        #pragma unroll
        for(int it=0; it<8; it++){
            int r = it*2 + (lane>>4);
            int p = pb + r;
            u32 a0,a1,a2,a3;
            lds128(a0,a1,a2,a3, sAb + (u32)((r*SAS + (lane&15)*8)*2));
            if(p<NPAIR){
                uint4 v={a0,a1,a2,a3};
                *(uint4*)&d_HRh[(size_t)p*64 + (lane&15)*4] = v;
            }
        }
        // ---- GEMM2 ----
        float c2[8][4];
        #pragma unroll
        for(int i=0;i<8;i++){ c2[i][0]=0.f;c2[i][1]=0.f;c2[i][2]=0.f;c2[i][3]=0.f; }
        #pragma unroll
        for(int kk=0;kk<8;kk++){
            u32 a0,a1,a2,a3;
            ldm4(a0,a1,a2,a3, aAddr + kk*32);
            #pragma unroll
            for(int np=0;np<4;np++){
                u32 b0,b1,b2r,b3;
                ldm4(b0,b1,b2r,b3, sWrb + bLpart + (u32)(np*16*SAS*2) + kk*32);
                mma16816(c2[np*2],   a0,a1,a2,a3, b0,b1);
                mma16816(c2[np*2+1], a0,a1,a2,a3, b2r,b3);
            }
        }
        __syncwarp();
        // ---- epilogue2: stage GA into sA, then coalesced copy ----
        #pragma unroll
        for(int nt=0;nt<8;nt++){
            int col = nt*8 + cpair;
            sts32(sAb+(u32)((rquad*SAS+col)*2),     bf2(c2[nt][0],c2[nt][1]));
            sts32(sAb+(u32)(((rquad+8)*SAS+col)*2), bf2(c2[nt][2],c2[nt][3]));
        }
        __syncwarp();
        #pragma unroll
        for(int it=0; it<4; it++){
            int r = it*4 + (lane>>3);
            int p = pb + r;
            u32 a0,a1,a2,a3;
            lds128(a0,a1,a2,a3, sAb + (u32)((r*SAS + (lane&7)*8)*2));
            if(p<NPAIR){
                uint4 v={a0,a1,a2,a3};
                *(uint4*)&d_GAh[(size_t)p*32 + (lane&7)*4] = v;
            }
        }
        __syncwarp();
    }
}

// ===================== per-edge kernel (atomic scatter) =====================
__global__ __launch_bounds__(256) void kD(const int* __restrict__ edges, const float* __restrict__ hidden,
                                          const float* __restrict__ w_alpha, int nedge){
    int e_id=(blockIdx.x*blockDim.x+threadIdx.x)>>5;
    int lane=threadIdx.x&31;
    if(e_id>=nedge) return;
    const int* e = edges + (size_t)e_id*7;
    int r_idx=__ldg(e+0), rel=__ldg(e+2), sub=__ldg(e+4), obj=__ldg(e+5), tim=__ldg(e+6);
    int p = rel*MAXH + tim;
    int m0=lane*2;
    float2 g1=bf2f(__ldg(&d_HSWSh[(size_t)sub*32+lane]));
    float2 g2=bf2f(__ldg(&d_GAh[(size_t)p*32+lane]));
    float2 g3=bf2f(__ldg(&d_Tqrh[r_idx*32+lane]));
    float wa0=__ldg(&w_alpha[m0]), wa1=__ldg(&w_alpha[m0+1]);
    float s = lrelu(g1.x+g2.x+g3.x)*wa0 + lrelu(g1.y+g2.y+g3.y)*wa1;
    #pragma unroll
    for(int o=16;o;o>>=1) s += __shfl_xor_sync(0xffffffffu,s,o);
    float ea=__expf(s);
    float4 hs=*(const float4*)&hidden[(size_t)sub*128+lane*4];
    uint2 hrb= *(const uint2*)&d_HRh[(size_t)p*64+lane*2];
    float2 r01=bf2f(hrb.x), r23=bf2f(hrb.y);
    float4 m;
    m.x=ea*(hs.x+r01.x); m.y=ea*(hs.y+r01.y);
    m.z=ea*(hs.z+r23.x); m.w=ea*(hs.w+r23.y);
    float* up=&d_UP[(size_t)obj*128+lane*4];
    asm volatile("red.global.add.v4.f32 [%0], {%1,%2,%3,%4};"
                 :: "l"(up),"f"(m.x),"f"(m.y),"f"(m.z),"f"(m.w) : "memory");
    if(lane==0) atomicAdd(&d_BOT[obj], ea);
}

// ===================== final GEMM: 8 nodes per warp (weight LDS reuse) =====================
#define KE_NW 8
#define SMEM_E ((128*128 + 8*KE_NW*128)*4)

__global__ __launch_bounds__(256) void kE(const float* __restrict__ Wh, float* __restrict__ out){
    extern __shared__ float sm[];
    float* sW=sm;                                   // 128*128
    int warp=threadIdx.x>>5, lane=threadIdx.x&31;
    float* sX=sm + 128*128 + warp*KE_NW*128;
    for(int i=threadIdx.x;i<128*128;i+=256) sW[i]=Wh[i];
    __syncthreads();
    int k0=lane*4;
    for(int base=blockIdx.x*(8*KE_NW)+warp*KE_NW; base<NNODE; base+=gridDim.x*8*KE_NW){
        #pragma unroll
        for(int nn=0;nn<KE_NW;nn++){
            int n=base+nn; int nc=(n<NNODE)?n:(NNODE-1);
            float inv=1.f/(d_BOT[nc]+1e-5f);
            float4 u=*(const float4*)&d_UP[(size_t)nc*128+k0];
            float4 xx; xx.x=u.x*inv; xx.y=u.y*inv; xx.z=u.z*inv; xx.w=u.w*inv;
            *(float4*)&sX[nn*128+k0]=xx;
        }
        __syncwarp();
        u64 a01[KE_NW], a23[KE_NW];
        #pragma unroll
        for(int nn=0;nn<KE_NW;nn++){ a01[nn]=0ULL; a23[nn]=0ULL; }
        for(int j=0;j<128;j+=4){
            float4 xv[KE_NW];
            #pragma unroll
            for(int nn=0;nn<KE_NW;nn++) xv[nn]=*(const float4*)&sX[nn*128+j];
            #pragma unroll
            for(int jj=0;jj<4;jj++){
                ulonglong2 w=*(const ulonglong2*)&sW[(j+jj)*128+k0];
                #pragma unroll
                for(int nn=0;nn<KE_NW;nn++){
                    float v = (jj==0)?xv[nn].x:(jj==1)?xv[nn].y:(jj==2)?xv[nn].z:xv[nn].w;
                    u64 hb=pk2(v,v);
                    fma2(a01[nn],hb,w.x); fma2(a23[nn],hb,w.y);
                }
            }
        }
        #pragma unroll
        for(int nn=0;nn<KE_NW;nn++){
            int n=base+nn;
            if(n<NNODE){
                float4 r; upk2(a01[nn],r.x,r.y); upk2(a23[nn],r.z,r.w);
                *(float4*)&out[(size_t)n*128+k0]=r;
            }
        }
        __syncwarp();
    }
}

extern "C" void kernel_launch(void* const* d_in, const int* in_sizes, int n_in,
                              void* d_out, int out_size){
    const float* hidden =(const float*)d_in[0];
    const float* rela   =(const float*)d_in[1];
    const float* pe     =(const float*)d_in[2];
    const float* W1     =(const float*)d_in[3];
    const float* b1     =(const float*)d_in[4];
    const float* W2     =(const float*)d_in[5];
    const float* b2     =(const float*)d_in[6];
    const float* Ws     =(const float*)d_in[7];
    const float* Wr     =(const float*)d_in[8];
    const float* Wqr    =(const float*)d_in[9];
    const float* bqr    =(const float*)d_in[10];
    const float* w_alpha=(const float*)d_in[11];
    const float* Wh     =(const float*)d_in[12];
    const int*   q_rel  =(const int*)d_in[13];
    const int*   edges  =(const int*)d_in[14];
    float* out=(float*)d_out;
    int nedge = in_sizes[14]/7;

    cudaFuncSetAttribute(kC_mma, cudaFuncAttributeMaxDynamicSharedMemorySize, SMEM_C);
    cudaFuncSetAttribute(kE, cudaFuncAttributeMaxDynamicSharedMemorySize, SMEM_E);

    kInit<<<VOCAB+MAXH+NQ+NZB,128>>>(rela,W1,b1,pe,Wqr,q_rel,bqr);
    kB<<<296,256>>>(hidden,Ws);
    kC_mma<<<296,256,SMEM_C>>>(rela,W2,b2,Wr);
    kD<<<(nedge*32+255)/256,256>>>(edges,hidden,w_alpha,nedge);
    kE<<<296,256,SMEM_E>>>(Wh,out);
}

// round 12
// speedup vs baseline: 1.4489x; 1.0769x over previous
#include <cuda_runtime.h>
#include <cuda_bf16.h>
#include <math.h>

#define NNODE  50000
#define VOCAB  401
#define MAXH   1000
#define NPAIR  (VOCAB*MAXH)
#define NQ     512
#define NZB    1408   // zero-blocks inside kInit

// ---- device scratch ----
__device__ float d_TrelW1[VOCAB*128];      // rela@W1[0:128] + b1
__device__ float d_TtimW1[MAXH*128];
__device__ unsigned int d_Tqrh[NQ*32];     // bf16x2: rela[q_rel]@Wqr + bqr
__device__ unsigned int d_HSWSh[NNODE*32]; // bf16x2 hidden@Ws
__device__ unsigned int d_HRh[NPAIR*64];   // bf16x2 HR
__device__ unsigned int d_GAh[NPAIR*32];   // bf16x2 GA
__device__ float d_UP[NNODE*128];
__device__ float d_BOT[NNODE];

typedef unsigned long long u64;
typedef unsigned int u32;
__device__ __forceinline__ u64 pk2(float x, float y){ u64 r; asm("mov.b64 %0,{%1,%2};":"=l"(r):"f"(x),"f"(y)); return r; }
__device__ __forceinline__ void upk2(u64 v, float&x, float&y){ asm("mov.b64 {%0,%1},%2;":"=f"(x),"=f"(y):"l"(v)); }
__device__ __forceinline__ void fma2(u64&d, u64 a, u64 b){ asm("fma.rn.f32x2 %0,%1,%2,%0;":"+l"(d):"l"(a),"l"(b)); }
__device__ __forceinline__ float lrelu(float x){ return x>0.f ? x : 0.01f*x; }
__device__ __forceinline__ u32 bf2(float a, float b){ u32 r; asm("cvt.rn.bf16x2.f32 %0,%2,%1;":"=r"(r):"f"(a),"f"(b)); return r; }
__device__ __forceinline__ float2 bf2f(u32 v){ float2 r; r.x=__uint_as_float(v<<16); r.y=__uint_as_float(v&0xffff0000u); return r; }
__device__ __forceinline__ u32 s2u(const void* p){ u32 a; asm("{ .reg .u64 t; cvta.to.shared.u64 t,%1; cvt.u32.u64 %0,t; }":"=r"(a):"l"(p)); return a; }

// ===================== fused init: zero accumulators + all small tables =====================
__global__ __launch_bounds__(128) void kInit(const float* __restrict__ rela, const float* __restrict__ W1,
                                             const float* __restrict__ b1v, const float* __restrict__ pe,
                                             const float* __restrict__ Wqr, const int* __restrict__ q_rel,
                                             const float* __restrict__ bqr){
    int b=blockIdx.x, t=threadIdx.x;
    if(b<VOCAB){
        __shared__ float s[128];
        s[t]=rela[b*128+t];
        __syncthreads();
        float acc=b1v[t];
        #pragma unroll 8
        for(int i=0;i<128;i++) acc += s[i]*W1[i*128+t];
        d_TrelW1[b*128+t]=acc;
    } else if(b<VOCAB+MAXH){
        int bb=b-VOCAB;
        __shared__ float s2[32];
        if(t<32) s2[t]=pe[bb*32+t];
        __syncthreads();
        float acc=0.f;
        #pragma unroll
        for(int i=0;i<32;i++) acc += s2[i]*W1[(128+i)*128+t];
        d_TtimW1[bb*128+t]=acc;
    } else if(b<VOCAB+MAXH+NQ){
        int bb=b-(VOCAB+MAXH);
        __shared__ float s3[128];
        int rel=q_rel[bb];
        s3[t]=rela[rel*128+t];
        __syncthreads();
        if(t<64){
            float acc=bqr[t];
            #pragma unroll 8
            for(int i=0;i<128;i++) acc += s3[i]*Wqr[i*64+t];
            float accn=__shfl_down_sync(0xffffffffu,acc,1);
            if((t&1)==0) d_Tqrh[bb*32+(t>>1)]=bf2(acc,accn);
        }
    } else {
        int zb=b-(VOCAB+MAXH+NQ);
        int i0=zb*128+t, st=NZB*128;
        float4 z={0.f,0.f,0.f,0.f};
        for(int i=i0;i<NNODE*32;i+=st) ((float4*)d_UP)[i]=z;
        for(int i=i0;i<NNODE;i+=st) d_BOT[i]=0.f;
    }
}

// ===================== hidden@Ws -> bf16 =====================
__global__ __launch_bounds__(256) void kB(const float* __restrict__ hidden, const float* __restrict__ Ws){
    __shared__ float sW[128*64];
    __shared__ float sX[8][128];
    for(int i=threadIdx.x;i<128*64;i+=256) sW[i]=Ws[i];
    __syncthreads();
    int warp=threadIdx.x>>5, lane=threadIdx.x&31;
    int m0=lane*2;
    for(int n=blockIdx.x*8+warp; n<NNODE; n+=gridDim.x*8){
        *(float4*)&sX[warp][lane*4] = *(const float4*)&hidden[n*128+lane*4];
        __syncwarp();
        u64 acc=0ULL;
        #pragma unroll 16
        for(int j=0;j<128;j++){
            float v=sX[warp][j];
            u64 hvp=pk2(v,v);
            u64 w=*(const u64*)&sW[j*64+m0];
            fma2(acc,hvp,w);
        }
        float2 r; upk2(acc,r.x,r.y);
        d_HSWSh[(size_t)n*32+lane]=bf2(r.x,r.y);
        __syncwarp();
    }
}

// ===================== mma.sync pair kernel =====================
#define SAS 136
#define OFF_WR 34816
#define OFF_B2 52224
#define OFF_SA 52736
#define SMEM_C (OFF_SA+34816)

__device__ __forceinline__ void ldm4(u32&r0,u32&r1,u32&r2,u32&r3,u32 addr){
    asm volatile("ldmatrix.sync.aligned.m8n8.x4.shared.b16 {%0,%1,%2,%3},[%4];"
                 :"=r"(r0),"=r"(r1),"=r"(r2),"=r"(r3):"r"(addr));
}
__device__ __forceinline__ void mma16816(float* c, u32 a0,u32 a1,u32 a2,u32 a3, u32 b0,u32 b1){
    asm volatile("mma.sync.aligned.m16n8k16.row.col.f32.bf16.bf16.f32 "
        "{%0,%1,%2,%3},{%4,%5,%6,%7},{%8,%9},{%0,%1,%2,%3};"
        :"+f"(c[0]),"+f"(c[1]),"+f"(c[2]),"+f"(c[3])
        :"r"(a0),"r"(a1),"r"(a2),"r"(a3),"r"(b0),"r"(b1));
}
__device__ __forceinline__ void sts32(u32 addr, u32 v){ asm volatile("st.shared.b32 [%0],%1;"::"r"(addr),"r"(v):"memory"); }
__device__ __forceinline__ void lds128(u32&a0,u32&a1,u32&a2,u32&a3,u32 addr){
    asm volatile("ld.shared.v4.b32 {%0,%1,%2,%3},[%4];"
                 :"=r"(a0),"=r"(a1),"=r"(a2),"=r"(a3):"r"(addr));
}

__global__ __launch_bounds__(256) void kC_mma(const float* __restrict__ rela, const float* __restrict__ W2,
                                              const float* __restrict__ b2v, const float* __restrict__ Wr){
    extern __shared__ char smc[];
    __nv_bfloat16* sW2 = (__nv_bfloat16*)smc;
    __nv_bfloat16* sWr = (__nv_bfloat16*)(smc+OFF_WR);
    float* sB2 = (float*)(smc+OFF_B2);
    int tid=threadIdx.x, warp=tid>>5, lane=tid&31;

    {
        int n = tid & 127, kh = tid >> 7;
        for(int k=kh; k<128; k+=2) sW2[n*SAS+k] = __float2bfloat16(W2[k*128+n]);
        int n2 = tid & 63, kh2 = tid >> 6;
        for(int k=kh2; k<128; k+=4) sWr[n2*SAS+k] = __float2bfloat16(Wr[k*64+n2]);
        if(tid<128) sB2[tid] = b2v[tid];
    }
    __syncthreads();

    u32 sAb  = s2u(smc+OFF_SA) + warp*16*SAS*2;
    u32 sW2b = s2u(smc);
    u32 sWrb = s2u(smc+OFF_WR);

    u32 aAddr = sAb + (u32)(((lane&15)*SAS + (lane>>4)*8)*2);
    u32 bLpart = (u32)((((lane&7) + ((lane>>4)<<3))*SAS + ((lane>>3)&1)*8)*2);

    int rquad = lane>>2, cpair = (lane&3)*2;
    const int ngroup = (NPAIR+15)/16;

    for(int g=blockIdx.x*8+warp; g<ngroup; g+=gridDim.x*8){
        int pb = g*16;
        // ---- build A: h1 = lrelu(TrelW1+TtimW1+b1) bf16 ----
        #pragma unroll 4
        for(int rr=0; rr<16; rr++){
            int p = pb+rr; if(p>NPAIR-1) p=NPAIR-1;
            int rel=p/MAXH, tim=p-rel*MAXH;
            float4 a=*(const float4*)&d_TrelW1[rel*128+lane*4];
            float4 b=*(const float4*)&d_TtimW1[tim*128+lane*4];
            u32 lo=bf2(lrelu(a.x+b.x),lrelu(a.y+b.y));
            u32 hi=bf2(lrelu(a.z+b.z),lrelu(a.w+b.w));
            asm volatile("st.shared.v2.b32 [%0],{%1,%2};"
                         ::"r"(sAb+(u32)((rr*SAS+lane*4)*2)),"r"(lo),"r"(hi):"memory");
        }
        __syncwarp();
        // ---- GEMM1 ----
        float c[16][4];
        #pragma unroll
        for(int i=0;i<16;i++){ c[i][0]=0.f;c[i][1]=0.f;c[i][2]=0.f;c[i][3]=0.f; }
        #pragma unroll
        for(int kk=0;kk<8;kk++){
            u32 a0,a1,a2,a3;
            ldm4(a0,a1,a2,a3, aAddr + kk*32);
            #pragma unroll
            for(int np=0;np<8;np++){
                u32 b0,b1,b2r,b3;
                ldm4(b0,b1,b2r,b3, sW2b + bLpart + (u32)(np*16*SAS*2) + kk*32);
                mma16816(c[np*2],   a0,a1,a2,a3, b0,b1);
                mma16816(c[np*2+1], a0,a1,a2,a3, b2r,b3);
            }
        }
        // ---- epilogue1: hr -> sA (bf16) only ----
        {
            int p_a = pb + rquad, p_b = p_a + 8;
            int pac = p_a>NPAIR-1?NPAIR-1:p_a, pbc = p_b>NPAIR-1?NPAIR-1:p_b;
            const float* ra = rela + (pac/MAXH)*128;
            const float* rb = rela + (pbc/MAXH)*128;
            #pragma unroll
            for(int nt=0;nt<16;nt++){
                int col = nt*8 + cpair;
                float h0 = lrelu(c[nt][0]+sB2[col])   + __ldg(&ra[col]);
                float h1 = lrelu(c[nt][1]+sB2[col+1]) + __ldg(&ra[col+1]);
                float h2 = lrelu(c[nt][2]+sB2[col])   + __ldg(&rb[col]);
                float h3 = lrelu(c[nt][3]+sB2[col+1]) + __ldg(&rb[col+1]);
                sts32(sAb+(u32)((rquad*SAS+col)*2),     bf2(h0,h1));
                sts32(sAb+(u32)(((rquad+8)*SAS+col)*2), bf2(h2,h3));
            }
        }
        __syncwarp();
        // ---- coalesced HR copy: 2 rows (512B) per iteration ----
        #pragma unroll
        for(int it=0; it<8; it++){
            int r = it*2 + (lane>>4);
            int p = pb + r;
            u32 a0,a1,a2,a3;
            lds128(a0,a1,a2,a3, sAb + (u32)((r*SAS + (lane&15)*8)*2));
            if(p<NPAIR){
                uint4 v={a0,a1,a2,a3};
                *(uint4*)&d_HRh[(size_t)p*64 + (lane&15)*4] = v;
            }
        }
        // ---- GEMM2 ----
        float c2[8][4];
        #pragma unroll
        for(int i=0;i<8;i++){ c2[i][0]=0.f;c2[i][1]=0.f;c2[i][2]=0.f;c2[i][3]=0.f; }
        #pragma unroll
        for(int kk=0;kk<8;kk++){
            u32 a0,a1,a2,a3;
            ldm4(a0,a1,a2,a3, aAddr + kk*32);
            #pragma unroll
            for(int np=0;np<4;np++){
                u32 b0,b1,b2r,b3;
                ldm4(b0,b1,b2r,b3, sWrb + bLpart + (u32)(np*16*SAS*2) + kk*32);
                mma16816(c2[np*2],   a0,a1,a2,a3, b0,b1);
                mma16816(c2[np*2+1], a0,a1,a2,a3, b2r,b3);
            }
        }
        __syncwarp();
        // ---- epilogue2: stage GA into sA, then coalesced copy ----
        #pragma unroll
        for(int nt=0;nt<8;nt++){
            int col = nt*8 + cpair;
            sts32(sAb+(u32)((rquad*SAS+col)*2),     bf2(c2[nt][0],c2[nt][1]));
            sts32(sAb+(u32)(((rquad+8)*SAS+col)*2), bf2(c2[nt][2],c2[nt][3]));
        }
        __syncwarp();
        #pragma unroll
        for(int it=0; it<4; it++){
            int r = it*4 + (lane>>3);
            int p = pb + r;
            u32 a0,a1,a2,a3;
            lds128(a0,a1,a2,a3, sAb + (u32)((r*SAS + (lane&7)*8)*2));
            if(p<NPAIR){
                uint4 v={a0,a1,a2,a3};
                *(uint4*)&d_GAh[(size_t)p*32 + (lane&7)*4] = v;
            }
        }
        __syncwarp();
    }
}

// ===================== per-edge kernel: 2 edges per warp (ILP) =====================
__global__ __launch_bounds__(256) void kD(const int* __restrict__ edges, const float* __restrict__ hidden,
                                          const float* __restrict__ w_alpha, int nedge){
    int wid=(blockIdx.x*blockDim.x+threadIdx.x)>>5;
    int lane=threadIdx.x&31;
    int e0=wid*2, e1=wid*2+1;
    if(e0>=nedge) return;
    bool has1 = (e1<nedge);
    int e1c = has1? e1 : e0;

    const int* ea_=edges + (size_t)e0*7;
    const int* eb_=edges + (size_t)e1c*7;
    int r0=__ldg(ea_+0), rel0=__ldg(ea_+2), sub0=__ldg(ea_+4), obj0=__ldg(ea_+5), tim0=__ldg(ea_+6);
    int r1=__ldg(eb_+0), rel1=__ldg(eb_+2), sub1=__ldg(eb_+4), obj1=__ldg(eb_+5), tim1=__ldg(eb_+6);
    int p0=rel0*MAXH+tim0, p1=rel1*MAXH+tim1;
    int m0=lane*2;

    // issue all gathers up front (both edges) for max MLP
    u32 q1a=__ldg(&d_HSWSh[(size_t)sub0*32+lane]);
    u32 q1b=__ldg(&d_HSWSh[(size_t)sub1*32+lane]);
    u32 q2a=__ldg(&d_GAh[(size_t)p0*32+lane]);
    u32 q2b=__ldg(&d_GAh[(size_t)p1*32+lane]);
    u32 q3a=__ldg(&d_Tqrh[r0*32+lane]);
    u32 q3b=__ldg(&d_Tqrh[r1*32+lane]);
    float4 hs0=*(const float4*)&hidden[(size_t)sub0*128+lane*4];
    float4 hs1=*(const float4*)&hidden[(size_t)sub1*128+lane*4];
    uint2 hr0= *(const uint2*)&d_HRh[(size_t)p0*64+lane*2];
    uint2 hr1= *(const uint2*)&d_HRh[(size_t)p1*64+lane*2];
    float wa0=__ldg(&w_alpha[m0]), wa1=__ldg(&w_alpha[m0+1]);

    float2 g1a=bf2f(q1a), g2a=bf2f(q2a), g3a=bf2f(q3a);
    float2 g1b=bf2f(q1b), g2b=bf2f(q2b), g3b=bf2f(q3b);
    float sa = lrelu(g1a.x+g2a.x+g3a.x)*wa0 + lrelu(g1a.y+g2a.y+g3a.y)*wa1;
    float sb = lrelu(g1b.x+g2b.x+g3b.x)*wa0 + lrelu(g1b.y+g2b.y+g3b.y)*wa1;
    #pragma unroll
    for(int o=16;o;o>>=1){
        sa += __shfl_xor_sync(0xffffffffu,sa,o);
        sb += __shfl_xor_sync(0xffffffffu,sb,o);
    }
    float eaa=__expf(sa), eab=__expf(sb);

    float2 a01=bf2f(hr0.x), a23=bf2f(hr0.y);
    float2 b01=bf2f(hr1.x), b23=bf2f(hr1.y);
    float4 ma, mb;
    ma.x=eaa*(hs0.x+a01.x); ma.y=eaa*(hs0.y+a01.y);
    ma.z=eaa*(hs0.z+a23.x); ma.w=eaa*(hs0.w+a23.y);
    mb.x=eab*(hs1.x+b01.x); mb.y=eab*(hs1.y+b01.y);
    mb.z=eab*(hs1.z+b23.x); mb.w=eab*(hs1.w+b23.y);

    float* up0=&d_UP[(size_t)obj0*128+lane*4];
    asm volatile("red.global.add.v4.f32 [%0], {%1,%2,%3,%4};"
                 :: "l"(up0),"f"(ma.x),"f"(ma.y),"f"(ma.z),"f"(ma.w) : "memory");
    if(has1){
        float* up1=&d_UP[(size_t)obj1*128+lane*4];
        asm volatile("red.global.add.v4.f32 [%0], {%1,%2,%3,%4};"
                     :: "l"(up1),"f"(mb.x),"f"(mb.y),"f"(mb.z),"f"(mb.w) : "memory");
    }
    if(lane==0){
        atomicAdd(&d_BOT[obj0], eaa);
        if(has1) atomicAdd(&d_BOT[obj1], eab);
    }
}

// ===================== final GEMM: 8 nodes per warp (weight LDS reuse) =====================
#define KE_NW 8
#define SMEM_E ((128*128 + 8*KE_NW*128)*4)

__global__ __launch_bounds__(256) void kE(const float* __restrict__ Wh, float* __restrict__ out){
    extern __shared__ float sm[];
    float* sW=sm;                                   // 128*128
    int warp=threadIdx.x>>5, lane=threadIdx.x&31;
    float* sX=sm + 128*128 + warp*KE_NW*128;
    for(int i=threadIdx.x;i<128*128;i+=256) sW[i]=Wh[i];
    __syncthreads();
    int k0=lane*4;
    for(int base=blockIdx.x*(8*KE_NW)+warp*KE_NW; base<NNODE; base+=gridDim.x*8*KE_NW){
        #pragma unroll
        for(int nn=0;nn<KE_NW;nn++){
            int n=base+nn; int nc=(n<NNODE)?n:(NNODE-1);
            float inv=1.f/(d_BOT[nc]+1e-5f);
            float4 u=*(const float4*)&d_UP[(size_t)nc*128+k0];
            float4 xx; xx.x=u.x*inv; xx.y=u.y*inv; xx.z=u.z*inv; xx.w=u.w*inv;
            *(float4*)&sX[nn*128+k0]=xx;
        }
        __syncwarp();
        u64 a01[KE_NW], a23[KE_NW];
        #pragma unroll
        for(int nn=0;nn<KE_NW;nn++){ a01[nn]=0ULL; a23[nn]=0ULL; }
        for(int j=0;j<128;j+=4){
            float4 xv[KE_NW];
            #pragma unroll
            for(int nn=0;nn<KE_NW;nn++) xv[nn]=*(const float4*)&sX[nn*128+j];
            #pragma unroll
            for(int jj=0;jj<4;jj++){
                ulonglong2 w=*(const ulonglong2*)&sW[(j+jj)*128+k0];
                #pragma unroll
                for(int nn=0;nn<KE_NW;nn++){
                    float v = (jj==0)?xv[nn].x:(jj==1)?xv[nn].y:(jj==2)?xv[nn].z:xv[nn].w;
                    u64 hb=pk2(v,v);
                    fma2(a01[nn],hb,w.x); fma2(a23[nn],hb,w.y);
                }
            }
        }
        #pragma unroll
        for(int nn=0;nn<KE_NW;nn++){
            int n=base+nn;
            if(n<NNODE){
                float4 r; upk2(a01[nn],r.x,r.y); upk2(a23[nn],r.z,r.w);
                *(float4*)&out[(size_t)n*128+k0]=r;
            }
        }
        __syncwarp();
    }
}

extern "C" void kernel_launch(void* const* d_in, const int* in_sizes, int n_in,
                              void* d_out, int out_size){
    const float* hidden =(const float*)d_in[0];
    const float* rela   =(const float*)d_in[1];
    const float* pe     =(const float*)d_in[2];
    const float* W1     =(const float*)d_in[3];
    const float* b1     =(const float*)d_in[4];
    const float* W2     =(const float*)d_in[5];
    const float* b2     =(const float*)d_in[6];
    const float* Ws     =(const float*)d_in[7];
    const float* Wr     =(const float*)d_in[8];
    const float* Wqr    =(const float*)d_in[9];
    const float* bqr    =(const float*)d_in[10];
    const float* w_alpha=(const float*)d_in[11];
    const float* Wh     =(const float*)d_in[12];
    const int*   q_rel  =(const int*)d_in[13];
    const int*   edges  =(const int*)d_in[14];
    float* out=(float*)d_out;
    int nedge = in_sizes[14]/7;

    cudaFuncSetAttribute(kC_mma, cudaFuncAttributeMaxDynamicSharedMemorySize, SMEM_C);
    cudaFuncSetAttribute(kE, cudaFuncAttributeMaxDynamicSharedMemorySize, SMEM_E);

    int nwarp2 = (nedge+1)/2;   // warps needed at 2 edges/warp
    kInit<<<VOCAB+MAXH+NQ+NZB,128>>>(rela,W1,b1,pe,Wqr,q_rel,bqr);
    kB<<<296,256>>>(hidden,Ws);
    kC_mma<<<296,256,SMEM_C>>>(rela,W2,b2,Wr);
    kD<<<(nwarp2*32+255)/256,256>>>(edges,hidden,w_alpha,nedge);
    kE<<<296,256,SMEM_E>>>(Wh,out);
}